// round 14
// baseline (speedup 1.0000x reference)
#include <cuda_runtime.h>
#include <cuda_bf16.h>
#include <cstdint>

#define BB   2
#define SS   2048
#define DD   1024
#define HH   16
#define KVHn 4
#define HD   64
#define WIN  64
#define MM   (BB*SS)   // 4096

typedef unsigned long long ull;

__device__ __forceinline__ uint32_t smem_u32(const void* p) {
    uint32_t a;
    asm("{ .reg .u64 t; cvta.to.shared.u64 t, %1; cvt.u32.u64 %0, t; }"
        : "=r"(a) : "l"(p));
    return a;
}

// warp-level tensor core + async copy (plain sm_80+ ISA, no arch suffix)
__device__ __forceinline__ void ldsm4(uint32_t* r, uint32_t addr) {
    asm volatile("ldmatrix.sync.aligned.m8n8.x4.shared.b16 {%0,%1,%2,%3}, [%4];"
                 : "=r"(r[0]), "=r"(r[1]), "=r"(r[2]), "=r"(r[3]) : "r"(addr));
}
__device__ __forceinline__ void mma_tf32(float* c, const uint32_t* a, const uint32_t* b) {
    asm volatile(
        "mma.sync.aligned.m16n8k8.row.col.f32.tf32.tf32.f32 "
        "{%0,%1,%2,%3}, {%4,%5,%6,%7}, {%8,%9}, {%0,%1,%2,%3};"
        : "+f"(c[0]), "+f"(c[1]), "+f"(c[2]), "+f"(c[3])
        : "r"(a[0]), "r"(a[1]), "r"(a[2]), "r"(a[3]), "r"(b[0]), "r"(b[1]));
}
__device__ __forceinline__ uint32_t f2tf(uint32_t fbits) {
    uint32_t r;
    asm("cvt.rna.tf32.f32 %0, %1;" : "=r"(r) : "f"(__uint_as_float(fbits)));
    return r;
}
#define CPA16(dst, src) \
    asm volatile("cp.async.cg.shared.global [%0], [%1], 16;" :: "r"(dst), "l"(src) : "memory")
#define CPA_COMMIT() asm volatile("cp.async.commit_group;" ::: "memory")
#define CPA_WAIT0()  asm volatile("cp.async.wait_group 0;" ::: "memory")

// ---------------------------------------------------------------------------
// Device scratch
// ---------------------------------------------------------------------------
__device__ float g_q[MM * HH * HD];
__device__ float g_k[MM * KVHn * HD];
__device__ float g_v[MM * KVHn * HD];
__device__ float g_att[MM * HH * HD];       // attention output (tf32-rounded fp32)
__device__ float g_xt[MM * DD];             // x, tf32-rounded
__device__ float g_wt[1536 * DD];           // [wq|wk|wv]^T, tf32-rounded
__device__ float g_wo_t[DD * DD];           // wo^T, tf32-rounded

// ---------------------------------------------------------------------------
// Round x -> tf32 bits (so cp.async in the GEMM can copy raw).
// ---------------------------------------------------------------------------
__global__ __launch_bounds__(256) void round_x_kernel(
    const float* __restrict__ src, float* __restrict__ dst)
{
    const int i = (blockIdx.x * 256 + threadIdx.x) * 4;
    int4 v = *(const int4*)&src[i];
    int4 o;
    o.x = (int)f2tf((uint32_t)v.x);
    o.y = (int)f2tf((uint32_t)v.y);
    o.z = (int)f2tf((uint32_t)v.z);
    o.w = (int)f2tf((uint32_t)v.w);
    *(int4*)&dst[i] = o;
}

// ---------------------------------------------------------------------------
// Fused transpose of all 4 weight matrices (one launch), tf32-rounded output.
// x-tile 0-31: wq, 32-39: wk, 40-47: wv, 48-79: wo.
// ---------------------------------------------------------------------------
__global__ __launch_bounds__(256) void transpose_all_kernel(
    const float* __restrict__ wq, const float* __restrict__ wk,
    const float* __restrict__ wv, const float* __restrict__ wo,
    float* __restrict__ wt, float* __restrict__ wot)
{
    __shared__ float tile[32][33];
    int bx = blockIdx.x;
    const float* W; float* T; int N, rowOff;
    if (bx < 32)      { W = wq; T = wt;  N = 1024; rowOff = 0;    }
    else if (bx < 40) { W = wk; T = wt;  N = 256;  rowOff = 1024; bx -= 32; }
    else if (bx < 48) { W = wv; T = wt;  N = 256;  rowOff = 1280; bx -= 40; }
    else              { W = wo; T = wot; N = 1024; rowOff = 0;    bx -= 48; }
    const int tx = threadIdx.x, ty = threadIdx.y;
    const int n0 = bx * 32, k0 = blockIdx.y * 32;
    #pragma unroll
    for (int j = ty; j < 32; j += 8)
        tile[j][tx] = W[(k0 + j) * N + n0 + tx];
    __syncthreads();
    #pragma unroll
    for (int j = ty; j < 32; j += 8)
        T[(rowOff + n0 + j) * 1024 + k0 + tx] =
            __uint_as_float(f2tf(__float_as_uint(tile[tx][j])));
}

// ---------------------------------------------------------------------------
// tf32 HMMA GEMM v4: D[M,N] = A[M,1024] @ B[N,1024]^T, inputs pre-rounded.
// CTA tile 128x256, 256 threads, 8 warps (2m x 4n) x (64x64) warp tile.
// 2-stage cp.async pipeline, K-chunk 32, 48KB/stage = 96KB dynamic smem.
// XOR-swizzled 128B rows: granule c at row r lives at (c ^ (r&7)) -> ldmatrix
// conflict-free with zero padding.
// mode 0: qkv epilogue (RoPE -> g_q/g_k/g_v); mode 1: plain fp32 -> outp.
// ---------------------------------------------------------------------------
__global__ __launch_bounds__(256) void mma_gemm_kernel(
    const float* __restrict__ A, const float* __restrict__ B,
    const float* __restrict__ fc, const float* __restrict__ fs,
    float* __restrict__ outp, int mode)
{
    extern __shared__ __align__(16) float smx[];
    // stage layout: A [128 rows x 128B] at +0, B [256 rows x 128B] at +16384
    const uint32_t sb0 = smem_u32(smx);

    const int tid  = threadIdx.x;
    const int lane = tid & 31, wid = tid >> 5;
    const int wm = wid & 1, wn = wid >> 1;         // 2m x 4n, 64x64 tiles
    const int m0 = blockIdx.y * 128, n0 = blockIdx.x * 256;

    // ---- cp.async mapping ----
    // A: thread t -> row t>>1, granules (t&1)*4 .. +3   (4 x 16B)
    // B: thread t -> row t,   granules 0..7             (8 x 16B)
    const int ar = tid >> 1, ac0 = (tid & 1) * 4;
    const float* gA = &A[(m0 + ar) * 1024 + ac0 * 4];
    const float* gB = &B[(n0 + tid) * 1024];
    uint32_t dA[4], dB[8];
    #pragma unroll
    for (int i = 0; i < 4; i++)
        dA[i] = sb0 + ar * 128 + (((ac0 + i) ^ (ar & 7)) << 4);
    #pragma unroll
    for (int c = 0; c < 8; c++)
        dB[c] = sb0 + 16384 + tid * 128 + ((c ^ (tid & 7)) << 4);

    // ---- ldmatrix bases ----
    const int l15 = lane & 15, rx = lane & 7;
    const int hiA = (lane >> 4) & 1, hiB = (lane >> 3) & 1;
    const uint32_t baseA = sb0 + (wm * 64 + l15) * 128;
    const int browB = wn * 64 + (lane & 7) + ((lane & 16) ? 8 : 0);
    const uint32_t baseB = sb0 + 16384 + browB * 128;
    uint32_t swA[4], swB[4];
    #pragma unroll
    for (int k8 = 0; k8 < 4; k8++) {
        swA[k8] = (uint32_t)((((k8 << 1) | hiA) ^ rx) << 4);
        swB[k8] = (uint32_t)((((k8 << 1) | hiB) ^ rx) << 4);
    }

    float acc[4][8][4];
    #pragma unroll
    for (int i = 0; i < 4; i++)
        #pragma unroll
        for (int j = 0; j < 8; j++)
            #pragma unroll
            for (int q = 0; q < 4; q++) acc[i][j][q] = 0.f;

    #define ISSUE_STAGE(soff, go) do {                         \
        _Pragma("unroll")                                      \
        for (int i = 0; i < 4; i++)                            \
            CPA16(dA[i] + (soff), gA + (go) + i * 4);          \
        _Pragma("unroll")                                      \
        for (int c = 0; c < 8; c++)                            \
            CPA16(dB[c] + (soff), gB + (go) + c * 4);          \
    } while (0)

    ISSUE_STAGE(0, 0);
    CPA_COMMIT();

    for (int kc = 0; kc < 32; ++kc) {
        CPA_WAIT0();          // stage kc resident
        __syncthreads();      // visible; all warps done reading stage kc-1
        if (kc + 1 < 32) {
            ISSUE_STAGE(((kc + 1) & 1) * 49152, (kc + 1) * 32);
            CPA_COMMIT();     // lands during compute below
        }
        const uint32_t so = (kc & 1) * 49152;
        #pragma unroll
        for (int k8 = 0; k8 < 4; ++k8) {
            uint32_t Af[4][4], Bf[8][2];
            #pragma unroll
            for (int mt = 0; mt < 4; mt++)
                ldsm4(Af[mt], baseA + so + mt * 2048 + swA[k8]);
            #pragma unroll
            for (int np = 0; np < 4; np++) {
                uint32_t t[4];
                ldsm4(t, baseB + so + np * 2048 + swB[k8]);
                Bf[2*np][0]   = t[0]; Bf[2*np][1]   = t[1];
                Bf[2*np+1][0] = t[2]; Bf[2*np+1][1] = t[3];
            }
            #pragma unroll
            for (int mt = 0; mt < 4; mt++)
                #pragma unroll
                for (int nt = 0; nt < 8; nt++)
                    mma_tf32(acc[mt][nt], Af[mt], Bf[nt]);
        }
    }

    // ---- epilogue (per-col segment routing; bounds are 8-aligned) ----
    const int g = lane >> 2, t2 = (lane & 3) * 2;
    #pragma unroll
    for (int mt = 0; mt < 4; mt++) {
        #pragma unroll
        for (int h2 = 0; h2 < 2; h2++) {
            const int row = m0 + wm * 64 + mt * 16 + g + h2 * 8;
            const int s   = row & (SS - 1);
            #pragma unroll
            for (int nt = 0; nt < 8; nt++) {
                const int n = n0 + wn * 64 + nt * 8 + t2;    // global col
                float v0 = acc[mt][nt][h2 * 2];
                float v1 = acc[mt][nt][h2 * 2 + 1];
                float* dst; int ld, cc; bool rope;
                if (mode == 1)     { dst = outp; ld = 1024; cc = n;        rope = false; }
                else if (n < 1024) { dst = g_q;  ld = 1024; cc = n;        rope = true;  }
                else if (n < 1280) { dst = g_k;  ld = 256;  cc = n - 1024; rope = true;  }
                else               { dst = g_v;  ld = 256;  cc = n - 1280; rope = false; }
                if (rope) {
                    const int j = (n & 63) >> 1;
                    float c  = fc[s * 32 + j];
                    float sn = fs[s * 32 + j];
                    float o0 = v0 * c  - v1 * sn;
                    float o1 = v0 * sn + v1 * c;
                    v0 = o0; v1 = o1;
                }
                *(float2*)&dst[row * ld + cc] = make_float2(v0, v1);
            }
        }
    }
}

// ---------------------------------------------------------------------------
// Tensor-core sliding-window attention, all-tf32 (R12, epilogue now emits
// tf32-rounded g_att so the oproj GEMM can cp.async raw bits).
// ---------------------------------------------------------------------------
__global__ __launch_bounds__(128) void attn_kernel()
{
    __shared__ __align__(16) float Ks[80 * 68];   // K tf32 [key][d]; later P [row][key] stride 84
    __shared__ __align__(16) float Vs[64 * 84];   // V tf32 [d][key]
    const int b   = blockIdx.z;
    const int kvh = blockIdx.y;
    const int qbase  = blockIdx.x * 16;
    const int kstart = qbase - WIN;
    const int tid = threadIdx.x;
    const int lane = tid & 31, w = tid >> 5;

    uint32_t* Vw = (uint32_t*)Vs;
    for (int i = tid; i < 80 * 16; i += 128) {
        const int row = i >> 4, c4 = (i & 15) * 4;
        const int key = kstart + row;
        float4 kv, vv;
        if (key >= 0) {
            const int gidx = ((b * SS + key) * KVHn + kvh) * 64 + c4;
            kv = *(const float4*)&g_k[gidx];
            vv = *(const float4*)&g_v[gidx];
        } else {
            kv = make_float4(0.f, 0.f, 0.f, 0.f);
            vv = kv;
        }
        int4 kt;
        kt.x = (int)f2tf(__float_as_uint(kv.x));
        kt.y = (int)f2tf(__float_as_uint(kv.y));
        kt.z = (int)f2tf(__float_as_uint(kv.z));
        kt.w = (int)f2tf(__float_as_uint(kv.w));
        *(int4*)&Ks[row * 68 + c4] = kt;
        Vw[(c4 + 0) * 84 + row] = f2tf(__float_as_uint(vv.x));
        Vw[(c4 + 1) * 84 + row] = f2tf(__float_as_uint(vv.y));
        Vw[(c4 + 2) * 84 + row] = f2tf(__float_as_uint(vv.z));
        Vw[(c4 + 3) * 84 + row] = f2tf(__float_as_uint(vv.w));
    }
    __syncthreads();

    const int r  = lane >> 2, cA = lane & 3;
    const int mr0 = 16 * w + r;
    const int mr1 = mr0 + 8;
    const int qg0 = qbase + (mr0 >> 2), h0i = kvh * 4 + (mr0 & 3);
    const int qg1 = qbase + (mr1 >> 2), h1i = kvh * 4 + (mr1 & 3);
    const float* qp0 = &g_q[((b * SS + qg0) * HH + h0i) * 64];
    const float* qp1 = &g_q[((b * SS + qg1) * HH + h1i) * 64];

    const int brow = (lane & 7) + ((lane & 16) ? 8 : 0);
    const uint32_t bbase = smem_u32(Ks) + brow * 272 + ((lane & 8) ? 16 : 0);

    float sc[10][4];
    #pragma unroll
    for (int t = 0; t < 10; t++)
        #pragma unroll
        for (int q = 0; q < 4; q++) sc[t][q] = 0.f;

    #pragma unroll
    for (int k8 = 0; k8 < 8; k8++) {
        uint32_t a[4];
        a[0] = f2tf(__float_as_uint(qp0[k8 * 8 + cA]));
        a[1] = f2tf(__float_as_uint(qp1[k8 * 8 + cA]));
        a[2] = f2tf(__float_as_uint(qp0[k8 * 8 + cA + 4]));
        a[3] = f2tf(__float_as_uint(qp1[k8 * 8 + cA + 4]));
        #pragma unroll
        for (int np = 0; np < 5; np++) {
            uint32_t t[4];
            ldsm4(t, bbase + np * 16 * 272 + k8 * 32);
            uint32_t b0[2] = {t[0], t[1]}, b1[2] = {t[2], t[3]};
            mma_tf32(sc[2 * np],     a, b0);
            mma_tf32(sc[2 * np + 1], a, b1);
        }
    }

    const int qiA = mr0 >> 2, qiB = mr1 >> 2;
    const int jlo = (kstart < 0) ? -kstart : 0;
    const int jmin0 = (qiA > jlo) ? qiA : jlo, jmax0 = qiA + WIN;
    const int jmin1 = (qiB > jlo) ? qiB : jlo, jmax1 = qiB + WIN;
    float mx0 = -1e30f, mx1 = -1e30f;
    #pragma unroll
    for (int t = 0; t < 10; t++) {
        const int jb = 8 * t + 2 * cA;
        #pragma unroll
        for (int e = 0; e < 2; e++) {
            const int j = jb + e;
            float v0 = sc[t][e]     * 0.125f;
            float v1 = sc[t][2 + e] * 0.125f;
            v0 = (j >= jmin0 && j <= jmax0) ? v0 : -1e30f;
            v1 = (j >= jmin1 && j <= jmax1) ? v1 : -1e30f;
            sc[t][e] = v0; sc[t][2 + e] = v1;
            mx0 = fmaxf(mx0, v0); mx1 = fmaxf(mx1, v1);
        }
    }
    mx0 = fmaxf(mx0, __shfl_xor_sync(0xffffffffu, mx0, 1));
    mx0 = fmaxf(mx0, __shfl_xor_sync(0xffffffffu, mx0, 2));
    mx1 = fmaxf(mx1, __shfl_xor_sync(0xffffffffu, mx1, 1));
    mx1 = fmaxf(mx1, __shfl_xor_sync(0xffffffffu, mx1, 2));
    float sm0 = 0.f, sm1 = 0.f;
    #pragma unroll
    for (int t = 0; t < 10; t++) {
        #pragma unroll
        for (int e = 0; e < 2; e++) {
            float p0 = __expf(sc[t][e]     - mx0);
            float p1 = __expf(sc[t][2 + e] - mx1);
            sc[t][e] = p0; sc[t][2 + e] = p1;
            sm0 += p0; sm1 += p1;
        }
    }
    sm0 += __shfl_xor_sync(0xffffffffu, sm0, 1);
    sm0 += __shfl_xor_sync(0xffffffffu, sm0, 2);
    sm1 += __shfl_xor_sync(0xffffffffu, sm1, 1);
    sm1 += __shfl_xor_sync(0xffffffffu, sm1, 2);
    const float inv0 = 1.f / sm0, inv1 = 1.f / sm1;

    __syncthreads();
    uint32_t* Ps = (uint32_t*)Ks;
    #pragma unroll
    for (int t = 0; t < 10; t++) {
        const int jb = 8 * t + 2 * cA;
        Ps[mr0 * 84 + jb]     = f2tf(__float_as_uint(sc[t][0]));
        Ps[mr0 * 84 + jb + 1] = f2tf(__float_as_uint(sc[t][1]));
        Ps[mr1 * 84 + jb]     = f2tf(__float_as_uint(sc[t][2]));
        Ps[mr1 * 84 + jb + 1] = f2tf(__float_as_uint(sc[t][3]));
    }
    __syncwarp();

    float oc[8][4];
    #pragma unroll
    for (int i = 0; i < 8; i++)
        #pragma unroll
        for (int q = 0; q < 4; q++) oc[i][q] = 0.f;

    const uint32_t aoff = smem_u32(Ks)
        + (16 * w + (lane & 7) + ((lane & 8) ? 8 : 0)) * 336 + ((lane & 16) ? 16 : 0);
    const uint32_t boff = smem_u32(Vs)
        + ((lane & 7) + ((lane & 16) ? 8 : 0)) * 336 + ((lane & 8) ? 16 : 0);
    #pragma unroll
    for (int k8 = 0; k8 < 10; k8++) {
        uint32_t Af[4];
        ldsm4(Af, aoff + k8 * 32);
        #pragma unroll
        for (int dd = 0; dd < 4; dd++) {
            uint32_t t[4];
            ldsm4(t, boff + dd * 16 * 336 + k8 * 32);
            uint32_t b0[2] = {t[0], t[1]}, b1[2] = {t[2], t[3]};
            mma_tf32(oc[2 * dd],     Af, b0);
            mma_tf32(oc[2 * dd + 1], Af, b1);
        }
    }

    // epilogue: tf32-rounded so oproj's cp.async copies clean bits
    float* o0 = &g_att[(b * SS + qg0) * 1024 + h0i * 64];
    float* o1 = &g_att[(b * SS + qg1) * 1024 + h1i * 64];
    #pragma unroll
    for (int nt = 0; nt < 8; nt++) {
        const int col = 8 * nt + 2 * cA;
        float a0 = __uint_as_float(f2tf(__float_as_uint(oc[nt][0] * inv0)));
        float a1 = __uint_as_float(f2tf(__float_as_uint(oc[nt][1] * inv0)));
        float b0 = __uint_as_float(f2tf(__float_as_uint(oc[nt][2] * inv1)));
        float b1 = __uint_as_float(f2tf(__float_as_uint(oc[nt][3] * inv1)));
        *(float2*)&o0[col] = make_float2(a0, a1);
        *(float2*)&o1[col] = make_float2(b0, b1);
    }
}

// ---------------------------------------------------------------------------
extern "C" void kernel_launch(void* const* d_in, const int* in_sizes, int n_in,
                              void* d_out, int out_size)
{
    const float* x  = (const float*)d_in[0];
    const float* fc = (const float*)d_in[1];
    const float* fs = (const float*)d_in[2];
    const float* wq = (const float*)d_in[3];
    const float* wk = (const float*)d_in[4];
    const float* wv = (const float*)d_in[5];
    const float* wo = (const float*)d_in[6];
    float* out = (float*)d_out;

    float *wt, *wot, *att, *xt;
    cudaGetSymbolAddress((void**)&wt,  g_wt);
    cudaGetSymbolAddress((void**)&wot, g_wo_t);
    cudaGetSymbolAddress((void**)&att, g_att);
    cudaGetSymbolAddress((void**)&xt,  g_xt);

    // allow 96KB dynamic smem for the GEMM (attribute set, not an allocation)
    cudaFuncSetAttribute(mma_gemm_kernel,
                         cudaFuncAttributeMaxDynamicSharedMemorySize, 98304);

    // input conditioning: transposes + tf32 pre-rounding
    transpose_all_kernel<<<dim3(80, 32), dim3(32, 8)>>>(wq, wk, wv, wo, wt, wot);
    round_x_kernel<<<MM * DD / 1024, 256>>>(x, xt);

    // QKV projection + RoPE (tf32 HMMA, 128x256 tiles, cp.async pipeline)
    mma_gemm_kernel<<<dim3(6, 32), 256, 98304>>>(xt, wt, fc, fs, nullptr, 0);
    // tensor-core attention (all tf32)
    attn_kernel<<<dim3(SS / 16, KVHn, BB), 128>>>();
    // output projection (tf32 HMMA)
    mma_gemm_kernel<<<dim3(4, 32), 256, 98304>>>(att, wot, nullptr, nullptr, out, 1);
}

// round 15
// speedup vs baseline: 1.0336x; 1.0336x over previous
#include <cuda_runtime.h>
#include <cuda_bf16.h>
#include <cstdint>

#define BB   2
#define SS   2048
#define DD   1024
#define HH   16
#define KVHn 4
#define HD   64
#define WIN  64
#define MM   (BB*SS)   // 4096

typedef unsigned long long ull;

__device__ __forceinline__ uint32_t smem_u32(const void* p) {
    uint32_t a;
    asm("{ .reg .u64 t; cvta.to.shared.u64 t, %1; cvt.u32.u64 %0, t; }"
        : "=r"(a) : "l"(p));
    return a;
}

// warp-level tensor core ops (plain sm_80+ ISA, no arch suffix)
__device__ __forceinline__ void ldsm4(uint32_t* r, uint32_t addr) {
    asm volatile("ldmatrix.sync.aligned.m8n8.x4.shared.b16 {%0,%1,%2,%3}, [%4];"
                 : "=r"(r[0]), "=r"(r[1]), "=r"(r[2]), "=r"(r[3]) : "r"(addr));
}
__device__ __forceinline__ void mma_tf32(float* c, const uint32_t* a, const uint32_t* b) {
    asm volatile(
        "mma.sync.aligned.m16n8k8.row.col.f32.tf32.tf32.f32 "
        "{%0,%1,%2,%3}, {%4,%5,%6,%7}, {%8,%9}, {%0,%1,%2,%3};"
        : "+f"(c[0]), "+f"(c[1]), "+f"(c[2]), "+f"(c[3])
        : "r"(a[0]), "r"(a[1]), "r"(a[2]), "r"(a[3]), "r"(b[0]), "r"(b[1]));
}
__device__ __forceinline__ uint32_t f2tf(uint32_t fbits) {
    uint32_t r;
    asm("cvt.rna.tf32.f32 %0, %1;" : "=r"(r) : "f"(__uint_as_float(fbits)));
    return r;
}

// ---------------------------------------------------------------------------
// Device scratch
// ---------------------------------------------------------------------------
__device__ float g_q[MM * HH * HD];
__device__ float g_k[MM * KVHn * HD];
__device__ float g_v[MM * KVHn * HD];
__device__ float g_att[MM * HH * HD];       // attention output (tf32-rounded)
__device__ float g_xt[MM * DD];             // x, tf32-rounded
__device__ float g_wt[1536 * DD];           // [wq|wk|wv]^T, tf32-rounded
__device__ float g_wo_t[DD * DD];           // wo^T, tf32-rounded

// ---------------------------------------------------------------------------
// Round x -> tf32 bits (GEMM then copies raw, no cvt in its hot loop).
// ---------------------------------------------------------------------------
__global__ __launch_bounds__(256) void round_x_kernel(
    const float* __restrict__ src, float* __restrict__ dst)
{
    const int i = (blockIdx.x * 256 + threadIdx.x) * 4;
    int4 v = *(const int4*)&src[i];
    int4 o;
    o.x = (int)f2tf((uint32_t)v.x);
    o.y = (int)f2tf((uint32_t)v.y);
    o.z = (int)f2tf((uint32_t)v.z);
    o.w = (int)f2tf((uint32_t)v.w);
    *(int4*)&dst[i] = o;
}

// ---------------------------------------------------------------------------
// Fused transpose of all 4 weight matrices (one launch), tf32-rounded output.
// x-tile 0-31: wq, 32-39: wk, 40-47: wv, 48-79: wo.
// ---------------------------------------------------------------------------
__global__ __launch_bounds__(256) void transpose_all_kernel(
    const float* __restrict__ wq, const float* __restrict__ wk,
    const float* __restrict__ wv, const float* __restrict__ wo,
    float* __restrict__ wt, float* __restrict__ wot)
{
    __shared__ float tile[32][33];
    int bx = blockIdx.x;
    const float* W; float* T; int N, rowOff;
    if (bx < 32)      { W = wq; T = wt;  N = 1024; rowOff = 0;    }
    else if (bx < 40) { W = wk; T = wt;  N = 256;  rowOff = 1024; bx -= 32; }
    else if (bx < 48) { W = wv; T = wt;  N = 256;  rowOff = 1280; bx -= 40; }
    else              { W = wo; T = wot; N = 1024; rowOff = 0;    bx -= 48; }
    const int tx = threadIdx.x, ty = threadIdx.y;
    const int n0 = bx * 32, k0 = blockIdx.y * 32;
    #pragma unroll
    for (int j = ty; j < 32; j += 8)
        tile[j][tx] = W[(k0 + j) * N + n0 + tx];
    __syncthreads();
    #pragma unroll
    for (int j = ty; j < 32; j += 8)
        T[(rowOff + n0 + j) * 1024 + k0 + tx] =
            __uint_as_float(f2tf(__float_as_uint(tile[tx][j])));
}

// ---------------------------------------------------------------------------
// tf32 HMMA GEMM v5: D[M,N] = A[M,1024] @ B[N,1024]^T, inputs pre-rounded.
// CTA tile 128x256, 256 threads, 8 warps (2m x 4n) x (64x64) warp tiles.
// Single-buffered smem (A 128x36 + B 256x36 floats = 55.3KB dynamic),
// 144B-padded rows (R12-proven conflict-free ldmatrix addressing),
// register prefetch of the next K=32 chunk overlapping the MMAs.
// mode 0: qkv epilogue (RoPE -> g_q/g_k/g_v); mode 1: plain fp32 -> outp.
// ---------------------------------------------------------------------------
__global__ __launch_bounds__(256) void mma_gemm_kernel(
    const float* __restrict__ A, const float* __restrict__ B,
    const float* __restrict__ fc, const float* __restrict__ fs,
    float* __restrict__ outp, int mode)
{
    extern __shared__ __align__(16) float smx[];
    float* sA = smx;                 // 128 rows x 36 floats
    float* sB = smx + 128 * 36;      // 256 rows x 36 floats

    const int tid  = threadIdx.x;
    const int lane = tid & 31, wid = tid >> 5;
    const int wm = wid & 1, wn = wid >> 1;       // 2m x 4n, 64x64 warp tiles
    const int m0 = blockIdx.y * 128, n0 = blockIdx.x * 256;

    // ---- gmem load mapping ----
    // A: thread t -> row t>>1, 16 floats at (t&1)*16   (4 int4)
    // B: thread t -> row t,    32 floats               (8 int4)
    const int ar = tid >> 1, ac = (tid & 1) * 16;
    const float* pA = &A[(m0 + ar) * 1024 + ac];
    const float* pB = &B[(n0 + tid) * 1024];
    const int ssa = ar * 36 + ac;
    const int ssb = tid * 36;

    // ---- ldmatrix address bases (R12-proven pattern, 144B stride) ----
    const int arow = wm * 64 + (lane & 7) + ((lane & 8) ? 8 : 0);
    const uint32_t a_base = arow * 144 + ((lane & 16) ? 16 : 0);
    const int brow = wn * 64 + (lane & 7) + ((lane & 16) ? 8 : 0);
    const uint32_t b_base = brow * 144 + ((lane & 8) ? 16 : 0);
    const uint32_t uA = smem_u32(sA) + a_base;
    const uint32_t uB = smem_u32(sB) + b_base;

    float acc[4][8][4];
    #pragma unroll
    for (int i = 0; i < 4; i++)
        #pragma unroll
        for (int j = 0; j < 8; j++)
            #pragma unroll
            for (int q = 0; q < 4; q++) acc[i][j][q] = 0.f;

    int4 pr[12];
    #define PREF(koff) do {                                   \
        pr[0]  = *(const int4*)&pA[(koff)];                   \
        pr[1]  = *(const int4*)&pA[(koff) + 4];               \
        pr[2]  = *(const int4*)&pA[(koff) + 8];               \
        pr[3]  = *(const int4*)&pA[(koff) + 12];              \
        pr[4]  = *(const int4*)&pB[(koff)];                   \
        pr[5]  = *(const int4*)&pB[(koff) + 4];               \
        pr[6]  = *(const int4*)&pB[(koff) + 8];               \
        pr[7]  = *(const int4*)&pB[(koff) + 12];              \
        pr[8]  = *(const int4*)&pB[(koff) + 16];              \
        pr[9]  = *(const int4*)&pB[(koff) + 20];              \
        pr[10] = *(const int4*)&pB[(koff) + 24];              \
        pr[11] = *(const int4*)&pB[(koff) + 28];              \
    } while (0)

    PREF(0);
    for (int kc = 0; kc < 32; ++kc) {
        if (kc) __syncthreads();                 // prior reads done
        *(int4*)&sA[ssa]      = pr[0];
        *(int4*)&sA[ssa + 4]  = pr[1];
        *(int4*)&sA[ssa + 8]  = pr[2];
        *(int4*)&sA[ssa + 12] = pr[3];
        #pragma unroll
        for (int c = 0; c < 8; c++)
            *(int4*)&sB[ssb + c * 4] = pr[4 + c];
        __syncthreads();
        if (kc < 31) PREF((kc + 1) * 32);        // in flight during MMA

        #pragma unroll
        for (int k8 = 0; k8 < 4; ++k8) {
            const uint32_t kb = k8 * 32;         // 8 tf32 = 32 bytes
            uint32_t Af[4][4], Bf[8][2];
            #pragma unroll
            for (int mt = 0; mt < 4; mt++)
                ldsm4(Af[mt], uA + mt * 16 * 144 + kb);
            #pragma unroll
            for (int np = 0; np < 4; np++) {
                uint32_t t[4];
                ldsm4(t, uB + np * 16 * 144 + kb);
                Bf[2*np][0]   = t[0]; Bf[2*np][1]   = t[1];
                Bf[2*np+1][0] = t[2]; Bf[2*np+1][1] = t[3];
            }
            #pragma unroll
            for (int mt = 0; mt < 4; mt++)
                #pragma unroll
                for (int nt = 0; nt < 8; nt++)
                    mma_tf32(acc[mt][nt], Af[mt], Bf[nt]);
        }
    }

    // ---- epilogue (per-col segment routing; bounds are 8-aligned) ----
    const int g = lane >> 2, t2 = (lane & 3) * 2;
    #pragma unroll
    for (int mt = 0; mt < 4; mt++) {
        #pragma unroll
        for (int h2 = 0; h2 < 2; h2++) {
            const int row = m0 + wm * 64 + mt * 16 + g + h2 * 8;
            const int s   = row & (SS - 1);
            #pragma unroll
            for (int nt = 0; nt < 8; nt++) {
                const int n = n0 + wn * 64 + nt * 8 + t2;    // global col
                float v0 = acc[mt][nt][h2 * 2];
                float v1 = acc[mt][nt][h2 * 2 + 1];
                float* dst; int ld, cc; bool rope;
                if (mode == 1)     { dst = outp; ld = 1024; cc = n;        rope = false; }
                else if (n < 1024) { dst = g_q;  ld = 1024; cc = n;        rope = true;  }
                else if (n < 1280) { dst = g_k;  ld = 256;  cc = n - 1024; rope = true;  }
                else               { dst = g_v;  ld = 256;  cc = n - 1280; rope = false; }
                if (rope) {
                    const int j = (n & 63) >> 1;
                    float c  = fc[s * 32 + j];
                    float sn = fs[s * 32 + j];
                    float o0 = v0 * c  - v1 * sn;
                    float o1 = v0 * sn + v1 * c;
                    v0 = o0; v1 = o1;
                }
                *(float2*)&dst[row * ld + cc] = make_float2(v0, v1);
            }
        }
    }
}

// ---------------------------------------------------------------------------
// Tensor-core sliding-window attention, all-tf32 (R12/R13 version; epilogue
// emits tf32-rounded g_att so the oproj GEMM copies raw bits).
// ---------------------------------------------------------------------------
__global__ __launch_bounds__(128) void attn_kernel()
{
    __shared__ __align__(16) float Ks[80 * 68];   // K tf32 [key][d]; later P [row][key] stride 84
    __shared__ __align__(16) float Vs[64 * 84];   // V tf32 [d][key]
    const int b   = blockIdx.z;
    const int kvh = blockIdx.y;
    const int qbase  = blockIdx.x * 16;
    const int kstart = qbase - WIN;
    const int tid = threadIdx.x;
    const int lane = tid & 31, w = tid >> 5;

    uint32_t* Vw = (uint32_t*)Vs;
    for (int i = tid; i < 80 * 16; i += 128) {
        const int row = i >> 4, c4 = (i & 15) * 4;
        const int key = kstart + row;
        float4 kv, vv;
        if (key >= 0) {
            const int gidx = ((b * SS + key) * KVHn + kvh) * 64 + c4;
            kv = *(const float4*)&g_k[gidx];
            vv = *(const float4*)&g_v[gidx];
        } else {
            kv = make_float4(0.f, 0.f, 0.f, 0.f);
            vv = kv;
        }
        int4 kt;
        kt.x = (int)f2tf(__float_as_uint(kv.x));
        kt.y = (int)f2tf(__float_as_uint(kv.y));
        kt.z = (int)f2tf(__float_as_uint(kv.z));
        kt.w = (int)f2tf(__float_as_uint(kv.w));
        *(int4*)&Ks[row * 68 + c4] = kt;
        Vw[(c4 + 0) * 84 + row] = f2tf(__float_as_uint(vv.x));
        Vw[(c4 + 1) * 84 + row] = f2tf(__float_as_uint(vv.y));
        Vw[(c4 + 2) * 84 + row] = f2tf(__float_as_uint(vv.z));
        Vw[(c4 + 3) * 84 + row] = f2tf(__float_as_uint(vv.w));
    }
    __syncthreads();

    const int r  = lane >> 2, cA = lane & 3;
    const int mr0 = 16 * w + r;
    const int mr1 = mr0 + 8;
    const int qg0 = qbase + (mr0 >> 2), h0i = kvh * 4 + (mr0 & 3);
    const int qg1 = qbase + (mr1 >> 2), h1i = kvh * 4 + (mr1 & 3);
    const float* qp0 = &g_q[((b * SS + qg0) * HH + h0i) * 64];
    const float* qp1 = &g_q[((b * SS + qg1) * HH + h1i) * 64];

    const int brow = (lane & 7) + ((lane & 16) ? 8 : 0);
    const uint32_t bbase = smem_u32(Ks) + brow * 272 + ((lane & 8) ? 16 : 0);

    float sc[10][4];
    #pragma unroll
    for (int t = 0; t < 10; t++)
        #pragma unroll
        for (int q = 0; q < 4; q++) sc[t][q] = 0.f;

    #pragma unroll
    for (int k8 = 0; k8 < 8; k8++) {
        uint32_t a[4];
        a[0] = f2tf(__float_as_uint(qp0[k8 * 8 + cA]));
        a[1] = f2tf(__float_as_uint(qp1[k8 * 8 + cA]));
        a[2] = f2tf(__float_as_uint(qp0[k8 * 8 + cA + 4]));
        a[3] = f2tf(__float_as_uint(qp1[k8 * 8 + cA + 4]));
        #pragma unroll
        for (int np = 0; np < 5; np++) {
            uint32_t t[4];
            ldsm4(t, bbase + np * 16 * 272 + k8 * 32);
            uint32_t b0[2] = {t[0], t[1]}, b1[2] = {t[2], t[3]};
            mma_tf32(sc[2 * np],     a, b0);
            mma_tf32(sc[2 * np + 1], a, b1);
        }
    }

    const int qiA = mr0 >> 2, qiB = mr1 >> 2;
    const int jlo = (kstart < 0) ? -kstart : 0;
    const int jmin0 = (qiA > jlo) ? qiA : jlo, jmax0 = qiA + WIN;
    const int jmin1 = (qiB > jlo) ? qiB : jlo, jmax1 = qiB + WIN;
    float mx0 = -1e30f, mx1 = -1e30f;
    #pragma unroll
    for (int t = 0; t < 10; t++) {
        const int jb = 8 * t + 2 * cA;
        #pragma unroll
        for (int e = 0; e < 2; e++) {
            const int j = jb + e;
            float v0 = sc[t][e]     * 0.125f;
            float v1 = sc[t][2 + e] * 0.125f;
            v0 = (j >= jmin0 && j <= jmax0) ? v0 : -1e30f;
            v1 = (j >= jmin1 && j <= jmax1) ? v1 : -1e30f;
            sc[t][e] = v0; sc[t][2 + e] = v1;
            mx0 = fmaxf(mx0, v0); mx1 = fmaxf(mx1, v1);
        }
    }
    mx0 = fmaxf(mx0, __shfl_xor_sync(0xffffffffu, mx0, 1));
    mx0 = fmaxf(mx0, __shfl_xor_sync(0xffffffffu, mx0, 2));
    mx1 = fmaxf(mx1, __shfl_xor_sync(0xffffffffu, mx1, 1));
    mx1 = fmaxf(mx1, __shfl_xor_sync(0xffffffffu, mx1, 2));
    float sm0 = 0.f, sm1 = 0.f;
    #pragma unroll
    for (int t = 0; t < 10; t++) {
        #pragma unroll
        for (int e = 0; e < 2; e++) {
            float p0 = __expf(sc[t][e]     - mx0);
            float p1 = __expf(sc[t][2 + e] - mx1);
            sc[t][e] = p0; sc[t][2 + e] = p1;
            sm0 += p0; sm1 += p1;
        }
    }
    sm0 += __shfl_xor_sync(0xffffffffu, sm0, 1);
    sm0 += __shfl_xor_sync(0xffffffffu, sm0, 2);
    sm1 += __shfl_xor_sync(0xffffffffu, sm1, 1);
    sm1 += __shfl_xor_sync(0xffffffffu, sm1, 2);
    const float inv0 = 1.f / sm0, inv1 = 1.f / sm1;

    __syncthreads();
    uint32_t* Ps = (uint32_t*)Ks;
    #pragma unroll
    for (int t = 0; t < 10; t++) {
        const int jb = 8 * t + 2 * cA;
        Ps[mr0 * 84 + jb]     = f2tf(__float_as_uint(sc[t][0]));
        Ps[mr0 * 84 + jb + 1] = f2tf(__float_as_uint(sc[t][1]));
        Ps[mr1 * 84 + jb]     = f2tf(__float_as_uint(sc[t][2]));
        Ps[mr1 * 84 + jb + 1] = f2tf(__float_as_uint(sc[t][3]));
    }
    __syncwarp();

    float oc[8][4];
    #pragma unroll
    for (int i = 0; i < 8; i++)
        #pragma unroll
        for (int q = 0; q < 4; q++) oc[i][q] = 0.f;

    const uint32_t aoff = smem_u32(Ks)
        + (16 * w + (lane & 7) + ((lane & 8) ? 8 : 0)) * 336 + ((lane & 16) ? 16 : 0);
    const uint32_t boff = smem_u32(Vs)
        + ((lane & 7) + ((lane & 16) ? 8 : 0)) * 336 + ((lane & 8) ? 16 : 0);
    #pragma unroll
    for (int k8 = 0; k8 < 10; k8++) {
        uint32_t Af[4];
        ldsm4(Af, aoff + k8 * 32);
        #pragma unroll
        for (int dd = 0; dd < 4; dd++) {
            uint32_t t[4];
            ldsm4(t, boff + dd * 16 * 336 + k8 * 32);
            uint32_t b0[2] = {t[0], t[1]}, b1[2] = {t[2], t[3]};
            mma_tf32(oc[2 * dd],     Af, b0);
            mma_tf32(oc[2 * dd + 1], Af, b1);
        }
    }

    // epilogue: tf32-rounded so oproj's loads are clean raw bits
    float* o0 = &g_att[(b * SS + qg0) * 1024 + h0i * 64];
    float* o1 = &g_att[(b * SS + qg1) * 1024 + h1i * 64];
    #pragma unroll
    for (int nt = 0; nt < 8; nt++) {
        const int col = 8 * nt + 2 * cA;
        float a0 = __uint_as_float(f2tf(__float_as_uint(oc[nt][0] * inv0)));
        float a1 = __uint_as_float(f2tf(__float_as_uint(oc[nt][1] * inv0)));
        float b0 = __uint_as_float(f2tf(__float_as_uint(oc[nt][2] * inv1)));
        float b1 = __uint_as_float(f2tf(__float_as_uint(oc[nt][3] * inv1)));
        *(float2*)&o0[col] = make_float2(a0, a1);
        *(float2*)&o1[col] = make_float2(b0, b1);
    }
}

// ---------------------------------------------------------------------------
extern "C" void kernel_launch(void* const* d_in, const int* in_sizes, int n_in,
                              void* d_out, int out_size)
{
    const float* x  = (const float*)d_in[0];
    const float* fc = (const float*)d_in[1];
    const float* fs = (const float*)d_in[2];
    const float* wq = (const float*)d_in[3];
    const float* wk = (const float*)d_in[4];
    const float* wv = (const float*)d_in[5];
    const float* wo = (const float*)d_in[6];
    float* out = (float*)d_out;

    float *wt, *wot, *att, *xt;
    cudaGetSymbolAddress((void**)&wt,  g_wt);
    cudaGetSymbolAddress((void**)&wot, g_wo_t);
    cudaGetSymbolAddress((void**)&att, g_att);
    cudaGetSymbolAddress((void**)&xt,  g_xt);

    // 55.3KB dynamic smem for the GEMM (attribute set, not an allocation)
    const int smem_bytes = (128 * 36 + 256 * 36) * 4;   // 55296
    cudaFuncSetAttribute(mma_gemm_kernel,
                         cudaFuncAttributeMaxDynamicSharedMemorySize, smem_bytes);

    // input conditioning: transposes + tf32 pre-rounding
    transpose_all_kernel<<<dim3(80, 32), dim3(32, 8)>>>(wq, wk, wv, wo, wt, wot);
    round_x_kernel<<<MM * DD / 1024, 256>>>(x, xt);

    // QKV projection + RoPE (tf32 HMMA, 128x256 tiles, register prefetch)
    mma_gemm_kernel<<<dim3(6, 32), 256, smem_bytes>>>(xt, wt, fc, fs, nullptr, 0);
    // tensor-core attention (all tf32)
    attn_kernel<<<dim3(SS / 16, KVHn, BB), 128>>>();
    // output projection (tf32 HMMA)
    mma_gemm_kernel<<<dim3(4, 32), 256, smem_bytes>>>(att, wot, nullptr, nullptr, out, 1);
}

// round 16
// speedup vs baseline: 1.2759x; 1.2344x over previous
#include <cuda_runtime.h>
#include <cuda_bf16.h>
#include <cstdint>

#define BB   2
#define SS   2048
#define DD   1024
#define HH   16
#define KVHn 4
#define HD   64
#define WIN  64
#define MM   (BB*SS)   // 4096

typedef unsigned long long ull;

__device__ __forceinline__ uint32_t smem_u32(const void* p) {
    uint32_t a;
    asm("{ .reg .u64 t; cvta.to.shared.u64 t, %1; cvt.u32.u64 %0, t; }"
        : "=r"(a) : "l"(p));
    return a;
}

// warp-level tensor core ops (plain sm_80+ ISA, no arch suffix)
__device__ __forceinline__ void ldsm4(uint32_t* r, uint32_t addr) {
    asm volatile("ldmatrix.sync.aligned.m8n8.x4.shared.b16 {%0,%1,%2,%3}, [%4];"
                 : "=r"(r[0]), "=r"(r[1]), "=r"(r[2]), "=r"(r[3]) : "r"(addr));
}
__device__ __forceinline__ void mma_tf32(float* c, const uint32_t* a, const uint32_t* b) {
    asm volatile(
        "mma.sync.aligned.m16n8k8.row.col.f32.tf32.tf32.f32 "
        "{%0,%1,%2,%3}, {%4,%5,%6,%7}, {%8,%9}, {%0,%1,%2,%3};"
        : "+f"(c[0]), "+f"(c[1]), "+f"(c[2]), "+f"(c[3])
        : "r"(a[0]), "r"(a[1]), "r"(a[2]), "r"(a[3]), "r"(b[0]), "r"(b[1]));
}
__device__ __forceinline__ uint32_t f2tf(uint32_t fbits) {
    uint32_t r;
    asm("cvt.rna.tf32.f32 %0, %1;" : "=r"(r) : "f"(__uint_as_float(fbits)));
    return r;
}

// ---------------------------------------------------------------------------
// Device scratch
// ---------------------------------------------------------------------------
__device__ float g_q[MM * HH * HD];
__device__ float g_k[MM * KVHn * HD];
__device__ float g_v[MM * KVHn * HD];
__device__ float g_att[MM * HH * HD];       // attention output (tf32-rounded)
__device__ float g_xt[MM * DD];             // x, tf32-rounded
__device__ float g_wt[1536 * DD];           // [wq|wk|wv]^T, tf32-rounded
__device__ float g_wo_t[DD * DD];           // wo^T, tf32-rounded

// ---------------------------------------------------------------------------
// Fused input conditioning (ONE launch):
//   blocks [0, 2560): transpose+round the 4 weight matrices
//   blocks [2560, 6656): round x -> g_xt
// ---------------------------------------------------------------------------
__global__ __launch_bounds__(256) void condition_kernel(
    const float* __restrict__ x,
    const float* __restrict__ wq, const float* __restrict__ wk,
    const float* __restrict__ wv, const float* __restrict__ wo,
    float* __restrict__ xt, float* __restrict__ wt, float* __restrict__ wot)
{
    const int tid = threadIdx.x;
    if (blockIdx.x >= 2560) {
        // ---- round x ----
        const int i = ((blockIdx.x - 2560) * 256 + tid) * 4;
        int4 v = *(const int4*)&x[i];
        int4 o;
        o.x = (int)f2tf((uint32_t)v.x);
        o.y = (int)f2tf((uint32_t)v.y);
        o.z = (int)f2tf((uint32_t)v.z);
        o.w = (int)f2tf((uint32_t)v.w);
        *(int4*)&xt[i] = o;
        return;
    }
    // ---- transpose + round one 32x32 weight tile ----
    __shared__ float tile[32][33];
    int bx = blockIdx.x % 80;
    const int ky = blockIdx.x / 80;
    const float* W; float* T; int N, rowOff;
    if (bx < 32)      { W = wq; T = wt;  N = 1024; rowOff = 0;    }
    else if (bx < 40) { W = wk; T = wt;  N = 256;  rowOff = 1024; bx -= 32; }
    else if (bx < 48) { W = wv; T = wt;  N = 256;  rowOff = 1280; bx -= 40; }
    else              { W = wo; T = wot; N = 1024; rowOff = 0;    bx -= 48; }
    const int tx = tid & 31, ty = tid >> 5;
    const int n0 = bx * 32, k0 = ky * 32;
    #pragma unroll
    for (int j = ty; j < 32; j += 8)
        tile[j][tx] = W[(k0 + j) * N + n0 + tx];
    __syncthreads();
    #pragma unroll
    for (int j = ty; j < 32; j += 8)
        T[(rowOff + n0 + j) * 1024 + k0 + tx] =
            __uint_as_float(f2tf(__float_as_uint(tile[tx][j])));
}

// ---------------------------------------------------------------------------
// tf32 HMMA GEMM (exact R12 structure; inputs pre-rounded so staging stores
// are raw int4 copies -- no cvt in the hot loop).
// D = A[M,1024] @ B[N,1024]^T. 128x128x32 CTA tile, 8 warps x (64x32) warp
// tile, m16n8k8 MMA. 144B-padded smem rows, register prefetch, static smem.
// mode 0: qkv epilogue (RoPE -> g_q/g_k/g_v); mode 1: plain fp32 -> outp.
// ---------------------------------------------------------------------------
__global__ __launch_bounds__(256) void mma_gemm_kernel(
    const float* __restrict__ A, const float* __restrict__ B,
    const float* __restrict__ fc, const float* __restrict__ fs,
    float* __restrict__ outp, int mode)
{
    __shared__ __align__(16) float sA[128 * 36];
    __shared__ __align__(16) float sB[128 * 36];

    const int tid  = threadIdx.x;
    const int lane = tid & 31, wid = tid >> 5;
    const int wm = wid & 1, wn = wid >> 1;
    const int m0 = blockIdx.y * 128, n0 = blockIdx.x * 128;

    const int lr = tid >> 1, lcw = (tid & 1) * 16;
    const float* pA = &A[(m0 + lr) * 1024 + lcw];
    const float* pB = &B[(n0 + lr) * 1024 + lcw];
    const int ss = lr * 36 + lcw;

    const int arow = wm * 64 + (lane & 7) + ((lane & 8) ? 8 : 0);
    const uint32_t a_base = arow * 144 + ((lane & 16) ? 16 : 0);
    const int brow = wn * 32 + (lane & 7) + ((lane & 16) ? 8 : 0);
    const uint32_t b_base = brow * 144 + ((lane & 8) ? 16 : 0);
    const uint32_t uA = smem_u32(sA) + a_base;
    const uint32_t uB = smem_u32(sB) + b_base;

    float acc[4][4][4];
    #pragma unroll
    for (int i = 0; i < 4; i++)
        #pragma unroll
        for (int j = 0; j < 4; j++)
            #pragma unroll
            for (int q = 0; q < 4; q++) acc[i][j][q] = 0.f;

    int4 pr[8];
    #define PREF(koff) do {                                   \
        pr[0] = *(const int4*)&pA[koff];                      \
        pr[1] = *(const int4*)&pA[(koff) + 4];                \
        pr[2] = *(const int4*)&pA[(koff) + 8];                \
        pr[3] = *(const int4*)&pA[(koff) + 12];               \
        pr[4] = *(const int4*)&pB[koff];                      \
        pr[5] = *(const int4*)&pB[(koff) + 4];                \
        pr[6] = *(const int4*)&pB[(koff) + 8];                \
        pr[7] = *(const int4*)&pB[(koff) + 12];               \
    } while (0)

    PREF(0);
    for (int kc = 0; kc < 32; ++kc) {
        if (kc) __syncthreads();
        *(int4*)&sA[ss]      = pr[0];        // raw copies: inputs pre-rounded
        *(int4*)&sA[ss + 4]  = pr[1];
        *(int4*)&sA[ss + 8]  = pr[2];
        *(int4*)&sA[ss + 12] = pr[3];
        *(int4*)&sB[ss]      = pr[4];
        *(int4*)&sB[ss + 4]  = pr[5];
        *(int4*)&sB[ss + 8]  = pr[6];
        *(int4*)&sB[ss + 12] = pr[7];
        __syncthreads();
        if (kc < 31) PREF((kc + 1) * 32);    // in flight during MMA

        #pragma unroll
        for (int ks = 0; ks < 4; ++ks) {
            const uint32_t kb = ks * 32;
            uint32_t Af[4][4], Bf[4][2];
            #pragma unroll
            for (int mt = 0; mt < 4; mt++)
                ldsm4(Af[mt], uA + mt * 16 * 144 + kb);
            #pragma unroll
            for (int np = 0; np < 2; np++) {
                uint32_t t[4];
                ldsm4(t, uB + np * 16 * 144 + kb);
                Bf[2*np][0]   = t[0]; Bf[2*np][1]   = t[1];
                Bf[2*np+1][0] = t[2]; Bf[2*np+1][1] = t[3];
            }
            #pragma unroll
            for (int mt = 0; mt < 4; mt++)
                #pragma unroll
                for (int nt = 0; nt < 4; nt++)
                    mma_tf32(acc[mt][nt], Af[mt], Bf[nt]);
        }
    }

    const int g = lane >> 2, t2 = (lane & 3) * 2;
    float* dst; int ld, coff; bool rope;
    if (mode == 1)      { dst = outp;  ld = 1024; coff = n0;        rope = false; }
    else if (n0 < 1024) { dst = g_q;   ld = 1024; coff = n0;        rope = true;  }
    else if (n0 < 1280) { dst = g_k;   ld = 256;  coff = n0 - 1024; rope = true;  }
    else                { dst = g_v;   ld = 256;  coff = n0 - 1280; rope = false; }

    #pragma unroll
    for (int mt = 0; mt < 4; mt++) {
        #pragma unroll
        for (int h2 = 0; h2 < 2; h2++) {
            const int row = m0 + wm * 64 + mt * 16 + g + h2 * 8;
            const int s   = row & (SS - 1);
            #pragma unroll
            for (int nt = 0; nt < 4; nt++) {
                const int col = wn * 32 + nt * 8 + t2;
                float v0 = acc[mt][nt][h2 * 2];
                float v1 = acc[mt][nt][h2 * 2 + 1];
                if (rope) {
                    const int j = ((n0 + col) & 63) >> 1;
                    float c  = fc[s * 32 + j];
                    float sn = fs[s * 32 + j];
                    float o0 = v0 * c  - v1 * sn;
                    float o1 = v0 * sn + v1 * c;
                    v0 = o0; v1 = o1;
                }
                *(float2*)&dst[row * ld + coff + col] = make_float2(v0, v1);
            }
        }
    }
}

// ---------------------------------------------------------------------------
// Tensor-core sliding-window attention, all-tf32 (R12 version; epilogue emits
// tf32-rounded g_att so the oproj GEMM copies raw bits).
// ---------------------------------------------------------------------------
__global__ __launch_bounds__(128) void attn_kernel()
{
    __shared__ __align__(16) float Ks[80 * 68];   // K tf32 [key][d]; later P [row][key] stride 84
    __shared__ __align__(16) float Vs[64 * 84];   // V tf32 [d][key]
    const int b   = blockIdx.z;
    const int kvh = blockIdx.y;
    const int qbase  = blockIdx.x * 16;
    const int kstart = qbase - WIN;
    const int tid = threadIdx.x;
    const int lane = tid & 31, w = tid >> 5;

    uint32_t* Vw = (uint32_t*)Vs;
    for (int i = tid; i < 80 * 16; i += 128) {
        const int row = i >> 4, c4 = (i & 15) * 4;
        const int key = kstart + row;
        float4 kv, vv;
        if (key >= 0) {
            const int gidx = ((b * SS + key) * KVHn + kvh) * 64 + c4;
            kv = *(const float4*)&g_k[gidx];
            vv = *(const float4*)&g_v[gidx];
        } else {
            kv = make_float4(0.f, 0.f, 0.f, 0.f);
            vv = kv;
        }
        int4 kt;
        kt.x = (int)f2tf(__float_as_uint(kv.x));
        kt.y = (int)f2tf(__float_as_uint(kv.y));
        kt.z = (int)f2tf(__float_as_uint(kv.z));
        kt.w = (int)f2tf(__float_as_uint(kv.w));
        *(int4*)&Ks[row * 68 + c4] = kt;
        Vw[(c4 + 0) * 84 + row] = f2tf(__float_as_uint(vv.x));
        Vw[(c4 + 1) * 84 + row] = f2tf(__float_as_uint(vv.y));
        Vw[(c4 + 2) * 84 + row] = f2tf(__float_as_uint(vv.z));
        Vw[(c4 + 3) * 84 + row] = f2tf(__float_as_uint(vv.w));
    }
    __syncthreads();

    const int r  = lane >> 2, cA = lane & 3;
    const int mr0 = 16 * w + r;
    const int mr1 = mr0 + 8;
    const int qg0 = qbase + (mr0 >> 2), h0i = kvh * 4 + (mr0 & 3);
    const int qg1 = qbase + (mr1 >> 2), h1i = kvh * 4 + (mr1 & 3);
    const float* qp0 = &g_q[((b * SS + qg0) * HH + h0i) * 64];
    const float* qp1 = &g_q[((b * SS + qg1) * HH + h1i) * 64];

    const int brow = (lane & 7) + ((lane & 16) ? 8 : 0);
    const uint32_t bbase = smem_u32(Ks) + brow * 272 + ((lane & 8) ? 16 : 0);

    float sc[10][4];
    #pragma unroll
    for (int t = 0; t < 10; t++)
        #pragma unroll
        for (int q = 0; q < 4; q++) sc[t][q] = 0.f;

    #pragma unroll
    for (int k8 = 0; k8 < 8; k8++) {
        uint32_t a[4];
        a[0] = f2tf(__float_as_uint(qp0[k8 * 8 + cA]));
        a[1] = f2tf(__float_as_uint(qp1[k8 * 8 + cA]));
        a[2] = f2tf(__float_as_uint(qp0[k8 * 8 + cA + 4]));
        a[3] = f2tf(__float_as_uint(qp1[k8 * 8 + cA + 4]));
        #pragma unroll
        for (int np = 0; np < 5; np++) {
            uint32_t t[4];
            ldsm4(t, bbase + np * 16 * 272 + k8 * 32);
            uint32_t b0[2] = {t[0], t[1]}, b1[2] = {t[2], t[3]};
            mma_tf32(sc[2 * np],     a, b0);
            mma_tf32(sc[2 * np + 1], a, b1);
        }
    }

    const int qiA = mr0 >> 2, qiB = mr1 >> 2;
    const int jlo = (kstart < 0) ? -kstart : 0;
    const int jmin0 = (qiA > jlo) ? qiA : jlo, jmax0 = qiA + WIN;
    const int jmin1 = (qiB > jlo) ? qiB : jlo, jmax1 = qiB + WIN;
    float mx0 = -1e30f, mx1 = -1e30f;
    #pragma unroll
    for (int t = 0; t < 10; t++) {
        const int jb = 8 * t + 2 * cA;
        #pragma unroll
        for (int e = 0; e < 2; e++) {
            const int j = jb + e;
            float v0 = sc[t][e]     * 0.125f;
            float v1 = sc[t][2 + e] * 0.125f;
            v0 = (j >= jmin0 && j <= jmax0) ? v0 : -1e30f;
            v1 = (j >= jmin1 && j <= jmax1) ? v1 : -1e30f;
            sc[t][e] = v0; sc[t][2 + e] = v1;
            mx0 = fmaxf(mx0, v0); mx1 = fmaxf(mx1, v1);
        }
    }
    mx0 = fmaxf(mx0, __shfl_xor_sync(0xffffffffu, mx0, 1));
    mx0 = fmaxf(mx0, __shfl_xor_sync(0xffffffffu, mx0, 2));
    mx1 = fmaxf(mx1, __shfl_xor_sync(0xffffffffu, mx1, 1));
    mx1 = fmaxf(mx1, __shfl_xor_sync(0xffffffffu, mx1, 2));
    float sm0 = 0.f, sm1 = 0.f;
    #pragma unroll
    for (int t = 0; t < 10; t++) {
        #pragma unroll
        for (int e = 0; e < 2; e++) {
            float p0 = __expf(sc[t][e]     - mx0);
            float p1 = __expf(sc[t][2 + e] - mx1);
            sc[t][e] = p0; sc[t][2 + e] = p1;
            sm0 += p0; sm1 += p1;
        }
    }
    sm0 += __shfl_xor_sync(0xffffffffu, sm0, 1);
    sm0 += __shfl_xor_sync(0xffffffffu, sm0, 2);
    sm1 += __shfl_xor_sync(0xffffffffu, sm1, 1);
    sm1 += __shfl_xor_sync(0xffffffffu, sm1, 2);
    const float inv0 = 1.f / sm0, inv1 = 1.f / sm1;

    __syncthreads();
    uint32_t* Ps = (uint32_t*)Ks;
    #pragma unroll
    for (int t = 0; t < 10; t++) {
        const int jb = 8 * t + 2 * cA;
        Ps[mr0 * 84 + jb]     = f2tf(__float_as_uint(sc[t][0]));
        Ps[mr0 * 84 + jb + 1] = f2tf(__float_as_uint(sc[t][1]));
        Ps[mr1 * 84 + jb]     = f2tf(__float_as_uint(sc[t][2]));
        Ps[mr1 * 84 + jb + 1] = f2tf(__float_as_uint(sc[t][3]));
    }
    __syncwarp();

    float oc[8][4];
    #pragma unroll
    for (int i = 0; i < 8; i++)
        #pragma unroll
        for (int q = 0; q < 4; q++) oc[i][q] = 0.f;

    const uint32_t aoff = smem_u32(Ks)
        + (16 * w + (lane & 7) + ((lane & 8) ? 8 : 0)) * 336 + ((lane & 16) ? 16 : 0);
    const uint32_t boff = smem_u32(Vs)
        + ((lane & 7) + ((lane & 16) ? 8 : 0)) * 336 + ((lane & 8) ? 16 : 0);
    #pragma unroll
    for (int k8 = 0; k8 < 10; k8++) {
        uint32_t Af[4];
        ldsm4(Af, aoff + k8 * 32);
        #pragma unroll
        for (int dd = 0; dd < 4; dd++) {
            uint32_t t[4];
            ldsm4(t, boff + dd * 16 * 336 + k8 * 32);
            uint32_t b0[2] = {t[0], t[1]}, b1[2] = {t[2], t[3]};
            mma_tf32(oc[2 * dd],     Af, b0);
            mma_tf32(oc[2 * dd + 1], Af, b1);
        }
    }

    // epilogue: tf32-rounded so oproj's staging copies are clean raw bits
    float* o0 = &g_att[(b * SS + qg0) * 1024 + h0i * 64];
    float* o1 = &g_att[(b * SS + qg1) * 1024 + h1i * 64];
    #pragma unroll
    for (int nt = 0; nt < 8; nt++) {
        const int col = 8 * nt + 2 * cA;
        float a0 = __uint_as_float(f2tf(__float_as_uint(oc[nt][0] * inv0)));
        float a1 = __uint_as_float(f2tf(__float_as_uint(oc[nt][1] * inv0)));
        float b0 = __uint_as_float(f2tf(__float_as_uint(oc[nt][2] * inv1)));
        float b1 = __uint_as_float(f2tf(__float_as_uint(oc[nt][3] * inv1)));
        *(float2*)&o0[col] = make_float2(a0, a1);
        *(float2*)&o1[col] = make_float2(b0, b1);
    }
}

// ---------------------------------------------------------------------------
extern "C" void kernel_launch(void* const* d_in, const int* in_sizes, int n_in,
                              void* d_out, int out_size)
{
    const float* x  = (const float*)d_in[0];
    const float* fc = (const float*)d_in[1];
    const float* fs = (const float*)d_in[2];
    const float* wq = (const float*)d_in[3];
    const float* wk = (const float*)d_in[4];
    const float* wv = (const float*)d_in[5];
    const float* wo = (const float*)d_in[6];
    float* out = (float*)d_out;

    float *wt, *wot, *att, *xt;
    cudaGetSymbolAddress((void**)&wt,  g_wt);
    cudaGetSymbolAddress((void**)&wot, g_wo_t);
    cudaGetSymbolAddress((void**)&att, g_att);
    cudaGetSymbolAddress((void**)&xt,  g_xt);

    // fused conditioning: weight transposes + x rounding, one launch
    condition_kernel<<<2560 + MM * DD / 1024, 256>>>(x, wq, wk, wv, wo, xt, wt, wot);

    // QKV projection + RoPE (tf32 HMMA, R12-proven config)
    mma_gemm_kernel<<<dim3(12, 32), 256>>>(xt, wt, fc, fs, nullptr, 0);
    // tensor-core attention (all tf32)
    attn_kernel<<<dim3(SS / 16, KVHn, BB), 128>>>();
    // output projection (tf32 HMMA)
    mma_gemm_kernel<<<dim3(8, 32), 256>>>(att, wot, nullptr, nullptr, out, 1);
}